// round 10
// baseline (speedup 1.0000x reference)
#include <cuda_runtime.h>
#include <cuda_bf16.h>
#include <math_constants.h>
#include <stdint.h>

#define MROWS 256      // 4*64 query rows
#define DDIM 768
#define NKEYS 2048
#define RDIM 12
#define TOPK 16
#define SPLIT1 4
#define SPLIT2 12
#define MN (MROWS * NKEYS)

#define G1_BLOCKS  128     // gemm1: 16 x 2 x 4
#define ADJ_BLOCKS 256     // adjsum: 8 rows per block

// ---------------- scratch (static device globals; no allocation) ------------
__device__ __align__(16) __nv_bfloat16 g_keysh [NKEYS * DDIM];
__device__ __align__(16) __nv_bfloat16 g_keysl [NKEYS * DDIM];
__device__ __align__(16) __nv_bfloat16 g_keysTh[DDIM * NKEYS];
__device__ __align__(16) __nv_bfloat16 g_keysTl[DDIM * NKEYS];
__device__ __align__(16) __nv_bfloat16 g_posh  [MROWS * DDIM];
__device__ __align__(16) __nv_bfloat16 g_posl  [MROWS * DDIM];
__device__ __align__(16) __nv_bfloat16 g_neih  [MROWS * NKEYS];
__device__ __align__(16) __nv_bfloat16 g_neil  [MROWS * NKEYS];
__device__ __align__(16) float g_adjsum [NKEYS * NKEYS];          // 16.8 MB
__device__ __align__(16) float g_scores4[SPLIT1 * MN];            // split-K buffers
__device__ __align__(16) float g_outp   [SPLIT2 * MROWS * DDIM];  // split-K buffers
__device__ float g_w[MROWS * TOPK];
__device__ int   g_idx[MROWS * TOPK];

// ---------------- generic PTX helpers (no sm_103a-only features) ------------
__device__ __forceinline__ uint32_t smem_u32(const void* p) {
    uint32_t a;
    asm("{ .reg .u64 t; cvta.to.shared.u64 t, %1; cvt.u32.u64 %0, t; }"
        : "=r"(a) : "l"(p));
    return a;
}

#define SWZ128(off) ((off) ^ (((off) >> 3) & 0x70))

__device__ __forceinline__ void cpasync16(uint32_t saddr, const void* g) {
    asm volatile("cp.async.cg.shared.global [%0], [%1], 16;"
                 :: "r"(saddr), "l"(g) : "memory");
}
#define CP_COMMIT() asm volatile("cp.async.commit_group;" ::: "memory")
#define CP_WAIT(n)  asm volatile("cp.async.wait_group %0;" :: "n"(n) : "memory")

__device__ __forceinline__ void ldm_x4(uint32_t* r, uint32_t addr) {
    asm volatile("ldmatrix.sync.aligned.m8n8.x4.shared.b16 {%0,%1,%2,%3}, [%4];"
                 : "=r"(r[0]), "=r"(r[1]), "=r"(r[2]), "=r"(r[3]) : "r"(addr));
}
__device__ __forceinline__ void ldm_x2(uint32_t* r, uint32_t addr) {
    asm volatile("ldmatrix.sync.aligned.m8n8.x2.shared.b16 {%0,%1}, [%2];"
                 : "=r"(r[0]), "=r"(r[1]) : "r"(addr));
}

__device__ __forceinline__ void mma16816(float* c, const uint32_t* a, const uint32_t* b) {
    asm volatile(
        "mma.sync.aligned.m16n8k16.row.col.f32.bf16.bf16.f32 "
        "{%0,%1,%2,%3}, {%4,%5,%6,%7}, {%8,%9}, {%0,%1,%2,%3};"
        : "+f"(c[0]), "+f"(c[1]), "+f"(c[2]), "+f"(c[3])
        : "r"(a[0]), "r"(a[1]), "r"(a[2]), "r"(a[3]), "r"(b[0]), "r"(b[1]));
}

// bf16 hi/lo packing helpers
__device__ __forceinline__ unsigned pack_hi2(float a, float b) {
    return (unsigned)__bfloat16_as_ushort(__float2bfloat16(a)) |
           ((unsigned)__bfloat16_as_ushort(__float2bfloat16(b)) << 16);
}
__device__ __forceinline__ unsigned pack_lo2(float a, float b) {
    float ra = a - __bfloat162float(__float2bfloat16(a));
    float rb = b - __bfloat162float(__float2bfloat16(b));
    return (unsigned)__bfloat16_as_ushort(__float2bfloat16(ra)) |
           ((unsigned)__bfloat16_as_ushort(__float2bfloat16(rb)) << 16);
}

// ---------------- kernel 1: fused keys-normalize + positions prep -----------
__global__ __launch_bounds__(256) void k_norm_prep(const float* __restrict__ kp,
                                                   const float* __restrict__ pos) {
    int tid = threadIdx.x;
    if (blockIdx.x < NKEYS) {
        int n = blockIdx.x;
        const float* row = kp + n * DDIM;
        float ssq = 0.f;
        for (int i = tid; i < DDIM; i += 256) { float v = row[i]; ssq = fmaf(v, v, ssq); }
        #pragma unroll
        for (int o = 16; o > 0; o >>= 1) ssq += __shfl_xor_sync(0xffffffffu, ssq, o);
        __shared__ float sr[8];
        if ((tid & 31) == 0) sr[tid >> 5] = ssq;
        __syncthreads();
        float tot = sr[0] + sr[1] + sr[2] + sr[3] + sr[4] + sr[5] + sr[6] + sr[7];
        float inv = rsqrtf(tot + 1e-12f);
        for (int i = tid; i < DDIM; i += 256) {
            float v = row[i] * inv;
            __nv_bfloat16 h = __float2bfloat16(v);
            g_keysh[n * DDIM + i] = h;
            g_keysl[n * DDIM + i] = __float2bfloat16(v - __bfloat162float(h));
        }
    } else {
        int i4 = (blockIdx.x - NKEYS) * 256 + tid;       // < 49152 float4s
        float4 v = ((const float4*)pos)[i4];
        uint2 H, L;
        H.x = pack_hi2(v.x, v.y); H.y = pack_hi2(v.z, v.w);
        L.x = pack_lo2(v.x, v.y); L.y = pack_lo2(v.z, v.w);
        ((uint2*)g_posh)[i4] = H;
        ((uint2*)g_posl)[i4] = L;
    }
}

// ---------------- kernel 2: transpose keys planes -> keysT ------------------
__global__ __launch_bounds__(256) void k_transpose() {
    __shared__ __nv_bfloat16 th[32][33], tl[32][33];
    int tx = threadIdx.x & 31, ty = threadIdx.x >> 5;    // 32 x 8
    int d0 = blockIdx.x * 32, n0 = blockIdx.y * 32;
    #pragma unroll
    for (int i = 0; i < 32; i += 8) {
        int n = n0 + ty + i, d = d0 + tx;
        th[ty + i][tx] = g_keysh[n * DDIM + d];
        tl[ty + i][tx] = g_keysl[n * DDIM + d];
    }
    __syncthreads();
    #pragma unroll
    for (int i = 0; i < 32; i += 8) {
        int d = d0 + ty + i, n = n0 + tx;
        g_keysTh[d * NKEYS + n] = th[tx][ty + i];
        g_keysTl[d * NKEYS + n] = tl[tx][ty + i];
    }
}

// ---------------- HMMA bf16-split NT GEMM tile body (Round-6 mainloop) ------
#define TILE_B   16384
#define STAGE_B  65536
__device__ __forceinline__
void gemm_tile(const __nv_bfloat16* __restrict__ Ah, const __nv_bfloat16* __restrict__ Al,
               const __nv_bfloat16* __restrict__ Bh, const __nv_bfloat16* __restrict__ Bl,
               float* __restrict__ Cbase, int K, int ldc,
               int bx, int by, int bz, int nz, char* smem) {
    const int tid = threadIdx.x, lane = tid & 31, wid = tid >> 5;
    const int warpM = wid >> 2, warpN = wid & 3;          // 2 x 4 warp grid
    const int col0 = bx * 128, row0 = by * 128;
    const int CH = K >> 6;
    const int base = CH / nz, rem = CH - base * nz;
    const int nch  = base + (bz < rem);
    const int kbeg = (bz * base + (bz < rem ? bz : rem)) * 64;
    float* C = Cbase + (size_t)bz * MROWS * ldc;
    const uint32_t sb0 = smem_u32(smem);

    float acc[4][4][4] = {};

    auto issue = [&](int stage, int k0) {
        uint32_t st = sb0 + stage * STAGE_B;
        #pragma unroll
        for (int t = 0; t < 4; t++) {
            const __nv_bfloat16* src = (t == 0) ? Ah : (t == 1) ? Al
                                      : (t == 2) ? Bh : Bl;
            int rbase = (t < 2) ? row0 : col0;
            #pragma unroll
            for (int j = 0; j < 4; j++) {
                int c = tid + 256 * j;                    // 0..1023
                int r = c >> 3, seg = c & 7;
                uint32_t so = st + t * TILE_B + SWZ128((uint32_t)(r * 128 + seg * 16));
                cpasync16(so, src + (size_t)(rbase + r) * K + k0 + seg * 8);
            }
        }
    };

    issue(0, kbeg);
    CP_COMMIT();

    const int rA = lane & 15, selA = lane >> 4;
    const int rB = lane & 7,  selB = (lane >> 3) & 1;

    for (int c = 0; c < nch; c++) {
        if (c + 1 < nch) { issue((c + 1) & 1, kbeg + (c + 1) * 64); CP_COMMIT(); CP_WAIT(1); }
        else             { CP_WAIT(0); }
        __syncthreads();
        uint32_t st = sb0 + (c & 1) * STAGE_B;
        uint32_t tAh = st, tAl = st + TILE_B, tBh = st + 2 * TILE_B, tBl = st + 3 * TILE_B;
        #pragma unroll
        for (int ks = 0; ks < 4; ks++) {
            uint32_t ah[4][4], al[4][4], bh[4][2], bl[4][2];
            #pragma unroll
            for (int tm = 0; tm < 4; tm++) {
                uint32_t off = SWZ128((uint32_t)((warpM * 64 + tm * 16 + rA) * 128 +
                                                 (ks * 16 + selA * 8) * 2));
                ldm_x4(ah[tm], tAh + off);
                ldm_x4(al[tm], tAl + off);
            }
            #pragma unroll
            for (int tn = 0; tn < 4; tn++) {
                uint32_t off = SWZ128((uint32_t)((warpN * 32 + tn * 8 + rB) * 128 +
                                                 (ks * 16 + selB * 8) * 2));
                ldm_x2(bh[tn], tBh + off);
                ldm_x2(bl[tn], tBl + off);
            }
            #pragma unroll
            for (int tm = 0; tm < 4; tm++)
                #pragma unroll
                for (int tn = 0; tn < 4; tn++) {
                    mma16816(acc[tm][tn], ah[tm], bh[tn]);
                    mma16816(acc[tm][tn], ah[tm], bl[tn]);
                    mma16816(acc[tm][tn], al[tm], bh[tn]);
                }
        }
        __syncthreads();
    }

    #pragma unroll
    for (int tm = 0; tm < 4; tm++) {
        int r0 = row0 + warpM * 64 + tm * 16 + (lane >> 2);
        #pragma unroll
        for (int tn = 0; tn < 4; tn++) {
            int col = col0 + warpN * 32 + tn * 8 + (lane & 3) * 2;
            *(float2*)&C[(size_t)r0 * ldc + col] =
                make_float2(acc[tm][tn][0], acc[tm][tn][1]);
            *(float2*)&C[(size_t)(r0 + 8) * ldc + col] =
                make_float2(acc[tm][tn][2], acc[tm][tn][3]);
        }
    }
}

// ---------------- kernel 3: fused gemm1 + adjacency reduction ---------------
// blocks [0, G1_BLOCKS): scores GEMM tile (16 x 2 x SPLIT1).
// blocks [G1_BLOCKS, +ADJ_BLOCKS): adj_sum over R, 8 rows per block.
__global__ __launch_bounds__(256)
void k_gemm_adj(const __nv_bfloat16* __restrict__ Ah, const __nv_bfloat16* __restrict__ Al,
                const __nv_bfloat16* __restrict__ Bh, const __nv_bfloat16* __restrict__ Bl,
                float* __restrict__ Cbase, int K, int ldc,
                const float* __restrict__ adj) {
    extern __shared__ char smem[];
    if (blockIdx.x < G1_BLOCKS) {
        int bx = blockIdx.x & 15, by = (blockIdx.x >> 4) & 1, bz = blockIdx.x >> 5;
        gemm_tile(Ah, Al, Bh, Bl, Cbase, K, ldc, bx, by, bz, SPLIT1, smem);
    } else {
        int ab = blockIdx.x - G1_BLOCKS;
        int tid = threadIdx.x;
        const float4* a = (const float4*)adj;
        const int stride = NKEYS * NKEYS / 4;            // 1,048,576
        #pragma unroll 1
        for (int rr = 0; rr < 8; rr++) {
            int base = (ab * 8 + rr) * (NKEYS / 4);
            float4 a0 = make_float4(0.f, 0.f, 0.f, 0.f);
            float4 a1 = make_float4(0.f, 0.f, 0.f, 0.f);
            #pragma unroll
            for (int r = 0; r < RDIM; r++) {
                float4 v0 = a[r * stride + base + tid];
                float4 v1 = a[r * stride + base + tid + 256];
                a0.x += v0.x; a0.y += v0.y; a0.z += v0.z; a0.w += v0.w;
                a1.x += v1.x; a1.y += v1.y; a1.z += v1.z; a1.w += v1.w;
            }
            ((float4*)g_adjsum)[base + tid]       = a0;
            ((float4*)g_adjsum)[base + tid + 256] = a1;
        }
    }
}

// ---------------- kernel 4: gemm2 (plain 3-D grid) --------------------------
__global__ __launch_bounds__(256)
void k_gemm(const __nv_bfloat16* __restrict__ Ah, const __nv_bfloat16* __restrict__ Al,
            const __nv_bfloat16* __restrict__ Bh, const __nv_bfloat16* __restrict__ Bl,
            float* __restrict__ Cbase, int K, int ldc) {
    extern __shared__ char smem[];
    gemm_tile(Ah, Al, Bh, Bl, Cbase, K, ldc,
              blockIdx.x, blockIdx.y, blockIdx.z, gridDim.z, smem);
}

// ---------------- kernel 5: top-16 + softmax (sorted register queues) -------
__device__ __forceinline__ unsigned long long tk_pack(float v, int idx) {
    unsigned u = __float_as_uint(v);
    u = (u & 0x80000000u) ? ~u : (u | 0x80000000u);
    return ((unsigned long long)u << 32) | (unsigned)(~idx);
}

#define TKCAS(i, j) { if (w[i] > w[j]) { unsigned long long t = w[i]; w[i] = w[j]; w[j] = t; } }

__global__ __launch_bounds__(256) void k_topk() {
    int row = blockIdx.x;
    int tid = threadIdx.x, wid = tid >> 5, lane = tid & 31;
    __shared__ unsigned long long cand[8 * TOPK];
    __shared__ unsigned long long sbest[TOPK];

    // load + pack once
    unsigned long long w[8];
    #pragma unroll
    for (int j = 0; j < 8; j++) {
        int n = wid * 256 + lane + 32 * j;
        int o = row * NKEYS + n;
        float s = g_scores4[o] + g_scores4[MN + o] +
                  g_scores4[2 * MN + o] + g_scores4[3 * MN + o];
        w[j] = tk_pack(s, n);
    }
    // sort ascending (19-comparator network); head = w[7]
    TKCAS(0,1) TKCAS(2,3) TKCAS(4,5) TKCAS(6,7)
    TKCAS(0,2) TKCAS(1,3) TKCAS(4,6) TKCAS(5,7)
    TKCAS(1,2) TKCAS(5,6) TKCAS(0,4) TKCAS(3,7)
    TKCAS(1,5) TKCAS(2,6)
    TKCAS(1,4) TKCAS(3,6)
    TKCAS(2,4) TKCAS(3,5)
    TKCAS(3,4)
    // 16 extraction rounds: warp-max of heads, winner pops its queue
    #pragma unroll 1
    for (int it = 0; it < TOPK; it++) {
        unsigned long long best = w[7];
        #pragma unroll
        for (int o = 16; o > 0; o >>= 1) {
            unsigned long long c = __shfl_xor_sync(0xffffffffu, best, o);
            if (c > best) best = c;
        }
        if (w[7] == best) {
            w[7] = w[6]; w[6] = w[5]; w[5] = w[4]; w[4] = w[3];
            w[3] = w[2]; w[2] = w[1]; w[1] = w[0]; w[0] = 0ull;
        }
        if (lane == 0) cand[wid * TOPK + it] = best;
    }
    __syncthreads();
    // warp 0 merges 128 candidates (4 per lane, sorted ascending queue)
    if (wid == 0) {
        unsigned long long c0 = cand[lane], c1 = cand[lane + 32],
                           c2 = cand[lane + 64], c3 = cand[lane + 96];
        // sort4 ascending
        { if (c0 > c1) { unsigned long long t = c0; c0 = c1; c1 = t; } }
        { if (c2 > c3) { unsigned long long t = c2; c2 = c3; c3 = t; } }
        { if (c0 > c2) { unsigned long long t = c0; c0 = c2; c2 = t; } }
        { if (c1 > c3) { unsigned long long t = c1; c1 = c3; c3 = t; } }
        { if (c1 > c2) { unsigned long long t = c1; c1 = c2; c2 = t; } }
        #pragma unroll 1
        for (int it = 0; it < TOPK; it++) {
            unsigned long long best = c3;
            #pragma unroll
            for (int o = 16; o > 0; o >>= 1) {
                unsigned long long t = __shfl_xor_sync(0xffffffffu, best, o);
                if (t > best) best = t;
            }
            if (c3 == best) { c3 = c2; c2 = c1; c1 = c0; c0 = 0ull; }
            if (lane == 0) sbest[it] = best;
        }
        if (lane == 0) {
            float vals[TOPK];
            #pragma unroll
            for (int i = 0; i < TOPK; i++) {
                unsigned u = (unsigned)(sbest[i] >> 32);
                unsigned vb = (u & 0x80000000u) ? (u & 0x7fffffffu) : ~u;
                vals[i] = __uint_as_float(vb);
            }
            float mx = vals[0], e[TOPK], sum = 0.f;
            #pragma unroll
            for (int i = 0; i < TOPK; i++) { e[i] = expf(vals[i] - mx); sum += e[i]; }
            float inv = 1.f / sum;
            #pragma unroll
            for (int i = 0; i < TOPK; i++) {
                g_w[row * TOPK + i]   = e[i] * inv;
                g_idx[row * TOPK + i] = (int)(~(unsigned)(sbest[i] & 0xffffffffull));
            }
        }
    }
}

// ---------------- kernel 6: nei gather -> hi/lo bf16 planes -----------------
__global__ __launch_bounds__(256) void k_nei() {
    int row = blockIdx.x;
    int tid = threadIdx.x;
    __shared__ float sw[TOPK];
    __shared__ int   si[TOPK];
    if (tid < TOPK) { sw[tid] = g_w[row * TOPK + tid]; si[tid] = g_idx[row * TOPK + tid]; }
    __syncthreads();
    int n0 = blockIdx.y * (NKEYS / 2) + tid * 4;
    float4 a0 = make_float4(0.f, 0.f, 0.f, 0.f);
    #pragma unroll
    for (int kk = 0; kk < TOPK; kk++) {
        float wv = sw[kk];
        float4 v0 = *(const float4*)&g_adjsum[si[kk] * NKEYS + n0];
        a0.x = fmaf(wv, v0.x, a0.x); a0.y = fmaf(wv, v0.y, a0.y);
        a0.z = fmaf(wv, v0.z, a0.z); a0.w = fmaf(wv, v0.w, a0.w);
    }
    uint2 H, L;
    H.x = pack_hi2(a0.x, a0.y); H.y = pack_hi2(a0.z, a0.w);
    L.x = pack_lo2(a0.x, a0.y); L.y = pack_lo2(a0.z, a0.w);
    *(uint2*)&g_neih[row * NKEYS + n0] = H;
    *(uint2*)&g_neil[row * NKEYS + n0] = L;
}

// ---------------- kernel 7: reduce split buffers -> d_out -------------------
__global__ __launch_bounds__(256) void k_reduce(float* __restrict__ out) {
    int i4 = blockIdx.x * 256 + threadIdx.x;       // < 49152 float4s
    const float4* p = (const float4*)g_outp;
    float4 a = make_float4(0.f, 0.f, 0.f, 0.f);
    #pragma unroll
    for (int z = 0; z < SPLIT2; z++) {
        float4 v = p[z * (MROWS * DDIM / 4) + i4];
        a.x += v.x; a.y += v.y; a.z += v.z; a.w += v.w;
    }
    ((float4*)out)[i4] = a;
}

// ---------------- launch ----------------------------------------------------
extern "C" void kernel_launch(void* const* d_in, const int* in_sizes, int n_in,
                              void* d_out, int out_size) {
    const float* positions  = (const float*)d_in[0];   // [4,64,768]
    const float* keys_param = (const float*)d_in[1];   // [2048,768]
    const float* adjacency  = (const float*)d_in[2];   // [12,2048,2048]
    float* out = (float*)d_out;                        // [4,64,768]

    __nv_bfloat16 *p_kh, *p_kl, *p_kth, *p_ktl, *p_ph, *p_pl, *p_nh, *p_nl;
    float *p_sc4, *p_outp;
    cudaGetSymbolAddress((void**)&p_kh,   g_keysh);
    cudaGetSymbolAddress((void**)&p_kl,   g_keysl);
    cudaGetSymbolAddress((void**)&p_kth,  g_keysTh);
    cudaGetSymbolAddress((void**)&p_ktl,  g_keysTl);
    cudaGetSymbolAddress((void**)&p_ph,   g_posh);
    cudaGetSymbolAddress((void**)&p_pl,   g_posl);
    cudaGetSymbolAddress((void**)&p_nh,   g_neih);
    cudaGetSymbolAddress((void**)&p_nl,   g_neil);
    cudaGetSymbolAddress((void**)&p_sc4,  g_scores4);
    cudaGetSymbolAddress((void**)&p_outp, g_outp);

    const int GEMM_SMEM = 2 * STAGE_B;      // 131072 bytes
    static int smem_set = 0;
    if (!smem_set) {
        cudaFuncSetAttribute(k_gemm, cudaFuncAttributeMaxDynamicSharedMemorySize,
                             GEMM_SMEM);
        cudaFuncSetAttribute(k_gemm_adj, cudaFuncAttributeMaxDynamicSharedMemorySize,
                             GEMM_SMEM);
        smem_set = 1;
    }

    // 1. fused: normalize keys -> hi/lo and positions -> hi/lo
    k_norm_prep<<<NKEYS + MROWS * DDIM / 4 / 256, 256>>>(keys_param, positions);
    // 2. keys transpose (for GEMM2's NT form)
    {
        dim3 grid(DDIM / 32, NKEYS / 32);
        k_transpose<<<grid, dim3(256)>>>();
    }
    // 3. fused: scores GEMM (128 CTAs) + full adjacency reduction (256 CTAs)
    k_gemm_adj<<<G1_BLOCKS + ADJ_BLOCKS, 256, GEMM_SMEM>>>(
        p_ph, p_pl, p_kh, p_kl, p_sc4, DDIM, NKEYS, adjacency);
    // 4. top-16 + softmax
    k_topk<<<MROWS, 256>>>();
    // 5. nei gather -> hi/lo planes
    {
        dim3 grid(MROWS, 2);
        k_nei<<<grid, 256>>>();
    }
    // 6. out = nei @ keys  (M=256, N=768, K=2048, split-K=12 -> 144 CTAs)
    {
        dim3 grid(DDIM / 128, MROWS / 128, SPLIT2);
        k_gemm<<<grid, 256, GEMM_SMEM>>>(p_nh, p_nl, p_kth, p_ktl, p_outp,
                                         NKEYS, DDIM);
    }
    // 7. reduce split buffers into d_out
    k_reduce<<<MROWS * DDIM / 4 / 256, 256>>>(out);
}

// round 12
// speedup vs baseline: 1.2363x; 1.2363x over previous
#include <cuda_runtime.h>
#include <cuda_bf16.h>
#include <math_constants.h>
#include <stdint.h>

#define MROWS 256      // 4*64 query rows
#define DDIM 768
#define NKEYS 2048
#define RDIM 12
#define TOPK 16
#define SPLIT1 4
#define SPLIT2 12
#define MN (MROWS * NKEYS)

// ---------------- scratch (static device globals; no allocation) ------------
__device__ __align__(16) __nv_bfloat16 g_keysh [NKEYS * DDIM];
__device__ __align__(16) __nv_bfloat16 g_keysl [NKEYS * DDIM];
__device__ __align__(16) __nv_bfloat16 g_keysTh[DDIM * NKEYS];
__device__ __align__(16) __nv_bfloat16 g_keysTl[DDIM * NKEYS];
__device__ __align__(16) __nv_bfloat16 g_posh  [MROWS * DDIM];
__device__ __align__(16) __nv_bfloat16 g_posl  [MROWS * DDIM];
__device__ __align__(16) __nv_bfloat16 g_neih  [MROWS * NKEYS];
__device__ __align__(16) __nv_bfloat16 g_neil  [MROWS * NKEYS];
__device__ __align__(16) float g_adjsum [NKEYS * NKEYS];          // 16.8 MB
__device__ __align__(16) float g_scores4[SPLIT1 * MN];            // split-K buffers
__device__ __align__(16) float g_outp   [SPLIT2 * MROWS * DDIM];  // split-K buffers
__device__ float g_w[MROWS * TOPK];
__device__ int   g_idx[MROWS * TOPK];
__device__ int   g_used[NKEYS];

// ---------------- generic PTX helpers (no sm_103a-only features) ------------
__device__ __forceinline__ uint32_t smem_u32(const void* p) {
    uint32_t a;
    asm("{ .reg .u64 t; cvta.to.shared.u64 t, %1; cvt.u32.u64 %0, t; }"
        : "=r"(a) : "l"(p));
    return a;
}

#define SWZ128(off) ((off) ^ (((off) >> 3) & 0x70))

__device__ __forceinline__ void cpasync16(uint32_t saddr, const void* g) {
    asm volatile("cp.async.cg.shared.global [%0], [%1], 16;"
                 :: "r"(saddr), "l"(g) : "memory");
}
#define CP_COMMIT() asm volatile("cp.async.commit_group;" ::: "memory")
#define CP_WAIT(n)  asm volatile("cp.async.wait_group %0;" :: "n"(n) : "memory")

__device__ __forceinline__ void ldm_x4(uint32_t* r, uint32_t addr) {
    asm volatile("ldmatrix.sync.aligned.m8n8.x4.shared.b16 {%0,%1,%2,%3}, [%4];"
                 : "=r"(r[0]), "=r"(r[1]), "=r"(r[2]), "=r"(r[3]) : "r"(addr));
}
__device__ __forceinline__ void ldm_x2(uint32_t* r, uint32_t addr) {
    asm volatile("ldmatrix.sync.aligned.m8n8.x2.shared.b16 {%0,%1}, [%2];"
                 : "=r"(r[0]), "=r"(r[1]) : "r"(addr));
}

__device__ __forceinline__ void mma16816(float* c, const uint32_t* a, const uint32_t* b) {
    asm volatile(
        "mma.sync.aligned.m16n8k16.row.col.f32.bf16.bf16.f32 "
        "{%0,%1,%2,%3}, {%4,%5,%6,%7}, {%8,%9}, {%0,%1,%2,%3};"
        : "+f"(c[0]), "+f"(c[1]), "+f"(c[2]), "+f"(c[3])
        : "r"(a[0]), "r"(a[1]), "r"(a[2]), "r"(a[3]), "r"(b[0]), "r"(b[1]));
}

// bf16 hi/lo packing helpers
__device__ __forceinline__ unsigned pack_hi2(float a, float b) {
    return (unsigned)__bfloat16_as_ushort(__float2bfloat16(a)) |
           ((unsigned)__bfloat16_as_ushort(__float2bfloat16(b)) << 16);
}
__device__ __forceinline__ unsigned pack_lo2(float a, float b) {
    float ra = a - __bfloat162float(__float2bfloat16(a));
    float rb = b - __bfloat162float(__float2bfloat16(b));
    return (unsigned)__bfloat16_as_ushort(__float2bfloat16(ra)) |
           ((unsigned)__bfloat16_as_ushort(__float2bfloat16(rb)) << 16);
}

// ---------------- kernel 1: fused keys-normalize + positions prep -----------
__global__ __launch_bounds__(256) void k_norm_prep(const float* __restrict__ kp,
                                                   const float* __restrict__ pos) {
    int tid = threadIdx.x;
    if (blockIdx.x < NKEYS) {
        int n = blockIdx.x;
        const float* row = kp + n * DDIM;
        float ssq = 0.f;
        for (int i = tid; i < DDIM; i += 256) { float v = row[i]; ssq = fmaf(v, v, ssq); }
        #pragma unroll
        for (int o = 16; o > 0; o >>= 1) ssq += __shfl_xor_sync(0xffffffffu, ssq, o);
        __shared__ float sr[8];
        if ((tid & 31) == 0) sr[tid >> 5] = ssq;
        __syncthreads();
        float tot = sr[0] + sr[1] + sr[2] + sr[3] + sr[4] + sr[5] + sr[6] + sr[7];
        float inv = rsqrtf(tot + 1e-12f);
        for (int i = tid; i < DDIM; i += 256) {
            float v = row[i] * inv;
            __nv_bfloat16 h = __float2bfloat16(v);
            g_keysh[n * DDIM + i] = h;
            g_keysl[n * DDIM + i] = __float2bfloat16(v - __bfloat162float(h));
        }
        if (tid == 0) g_used[n] = 0;
    } else {
        int i4 = (blockIdx.x - NKEYS) * 256 + tid;       // < 49152 float4s
        float4 v = ((const float4*)pos)[i4];
        uint2 H, L;
        H.x = pack_hi2(v.x, v.y); H.y = pack_hi2(v.z, v.w);
        L.x = pack_lo2(v.x, v.y); L.y = pack_lo2(v.z, v.w);
        ((uint2*)g_posh)[i4] = H;
        ((uint2*)g_posl)[i4] = L;
    }
}

// ---------------- kernel 2: transpose keys planes -> keysT ------------------
__global__ __launch_bounds__(256) void k_transpose() {
    __shared__ __nv_bfloat16 th[32][33], tl[32][33];
    int tx = threadIdx.x & 31, ty = threadIdx.x >> 5;    // 32 x 8
    int d0 = blockIdx.x * 32, n0 = blockIdx.y * 32;
    #pragma unroll
    for (int i = 0; i < 32; i += 8) {
        int n = n0 + ty + i, d = d0 + tx;
        th[ty + i][tx] = g_keysh[n * DDIM + d];
        tl[ty + i][tx] = g_keysl[n * DDIM + d];
    }
    __syncthreads();
    #pragma unroll
    for (int i = 0; i < 32; i += 8) {
        int d = d0 + ty + i, n = n0 + tx;
        g_keysTh[d * NKEYS + n] = th[tx][ty + i];
        g_keysTl[d * NKEYS + n] = tl[tx][ty + i];
    }
}

// ---------------- kernel 3: HMMA bf16-split NT GEMM (Round-6 mainloop) ------
#define TILE_B   16384
#define STAGE_B  65536
__global__ __launch_bounds__(256)
void k_gemm(const __nv_bfloat16* __restrict__ Ah, const __nv_bfloat16* __restrict__ Al,
            const __nv_bfloat16* __restrict__ Bh, const __nv_bfloat16* __restrict__ Bl,
            float* __restrict__ Cbase, int K, int ldc) {
    extern __shared__ char smem[];
    const int tid = threadIdx.x, lane = tid & 31, wid = tid >> 5;
    const int warpM = wid >> 2, warpN = wid & 3;          // 2 x 4 warp grid
    const int col0 = blockIdx.x * 128, row0 = blockIdx.y * 128;
    const int CH = K >> 6, nz = gridDim.z, z = blockIdx.z;
    const int base = CH / nz, rem = CH - base * nz;
    const int nch  = base + (z < rem);
    const int kbeg = (z * base + (z < rem ? z : rem)) * 64;
    float* C = Cbase + (size_t)z * MROWS * ldc;
    const uint32_t sb0 = smem_u32(smem);

    float acc[4][4][4] = {};

    auto issue = [&](int stage, int k0) {
        uint32_t st = sb0 + stage * STAGE_B;
        #pragma unroll
        for (int t = 0; t < 4; t++) {
            const __nv_bfloat16* src = (t == 0) ? Ah : (t == 1) ? Al
                                      : (t == 2) ? Bh : Bl;
            int rbase = (t < 2) ? row0 : col0;
            #pragma unroll
            for (int j = 0; j < 4; j++) {
                int c = tid + 256 * j;                    // 0..1023
                int r = c >> 3, seg = c & 7;
                uint32_t so = st + t * TILE_B + SWZ128((uint32_t)(r * 128 + seg * 16));
                cpasync16(so, src + (size_t)(rbase + r) * K + k0 + seg * 8);
            }
        }
    };

    issue(0, kbeg);
    CP_COMMIT();

    const int rA = lane & 15, selA = lane >> 4;
    const int rB = lane & 7,  selB = (lane >> 3) & 1;

    for (int c = 0; c < nch; c++) {
        if (c + 1 < nch) { issue((c + 1) & 1, kbeg + (c + 1) * 64); CP_COMMIT(); CP_WAIT(1); }
        else             { CP_WAIT(0); }
        __syncthreads();
        uint32_t st = sb0 + (c & 1) * STAGE_B;
        uint32_t tAh = st, tAl = st + TILE_B, tBh = st + 2 * TILE_B, tBl = st + 3 * TILE_B;
        #pragma unroll
        for (int ks = 0; ks < 4; ks++) {
            uint32_t ah[4][4], al[4][4], bh[4][2], bl[4][2];
            #pragma unroll
            for (int tm = 0; tm < 4; tm++) {
                uint32_t off = SWZ128((uint32_t)((warpM * 64 + tm * 16 + rA) * 128 +
                                                 (ks * 16 + selA * 8) * 2));
                ldm_x4(ah[tm], tAh + off);
                ldm_x4(al[tm], tAl + off);
            }
            #pragma unroll
            for (int tn = 0; tn < 4; tn++) {
                uint32_t off = SWZ128((uint32_t)((warpN * 32 + tn * 8 + rB) * 128 +
                                                 (ks * 16 + selB * 8) * 2));
                ldm_x2(bh[tn], tBh + off);
                ldm_x2(bl[tn], tBl + off);
            }
            #pragma unroll
            for (int tm = 0; tm < 4; tm++)
                #pragma unroll
                for (int tn = 0; tn < 4; tn++) {
                    mma16816(acc[tm][tn], ah[tm], bh[tn]);
                    mma16816(acc[tm][tn], ah[tm], bl[tn]);
                    mma16816(acc[tm][tn], al[tm], bh[tn]);
                }
        }
        __syncthreads();
    }

    #pragma unroll
    for (int tm = 0; tm < 4; tm++) {
        int r0 = row0 + warpM * 64 + tm * 16 + (lane >> 2);
        #pragma unroll
        for (int tn = 0; tn < 4; tn++) {
            int col = col0 + warpN * 32 + tn * 8 + (lane & 3) * 2;
            *(float2*)&C[(size_t)r0 * ldc + col] =
                make_float2(acc[tm][tn][0], acc[tm][tn][1]);
            *(float2*)&C[(size_t)(r0 + 8) * ldc + col] =
                make_float2(acc[tm][tn][2], acc[tm][tn][3]);
        }
    }
}

// ---------------- kernel 4: top-16 + softmax (lazy-rescan argmax, v4) -------
__device__ __forceinline__ unsigned long long tk_pack(float v, int idx) {
    unsigned u = __float_as_uint(v);
    u = (u & 0x80000000u) ? ~u : (u | 0x80000000u);
    return ((unsigned long long)u << 32) | (unsigned)(~idx);
}

__global__ __launch_bounds__(256) void k_topk() {
    int row = blockIdx.x;
    int tid = threadIdx.x, wid = tid >> 5, lane = tid & 31;
    __shared__ unsigned long long cand[8 * TOPK];
    __shared__ unsigned long long sbest[TOPK];

    // pack once; keep running per-thread max
    unsigned long long w[8];
    #pragma unroll
    for (int j = 0; j < 8; j++) {
        int n = wid * 256 + lane + 32 * j;
        int o = row * NKEYS + n;
        float s = g_scores4[o] + g_scores4[MN + o] +
                  g_scores4[2 * MN + o] + g_scores4[3 * MN + o];
        w[j] = tk_pack(s, n);
    }
    unsigned long long best = w[0];
    #pragma unroll
    for (int j = 1; j < 8; j++) if (w[j] > best) best = w[j];

    // 16 extraction rounds: warp argmax of bests; only winner rescans
    #pragma unroll 1
    for (int it = 0; it < TOPK; it++) {
        unsigned long long m = best;
        #pragma unroll
        for (int o = 16; o > 0; o >>= 1) {
            unsigned long long c = __shfl_xor_sync(0xffffffffu, m, o);
            if (c > m) m = c;
        }
        if (best == m) {                  // exactly one lane (idx in pack)
            #pragma unroll
            for (int j = 0; j < 8; j++) if (w[j] == m) w[j] = 0ull;
            best = w[0];
            #pragma unroll
            for (int j = 1; j < 8; j++) if (w[j] > best) best = w[j];
        }
        if (lane == 0) cand[wid * TOPK + it] = m;
    }
    __syncthreads();

    // warp 0 merges 128 candidates, same lazy scheme (4 per lane)
    if (wid == 0) {
        unsigned long long c[4];
        #pragma unroll
        for (int j = 0; j < 4; j++) c[j] = cand[lane + 32 * j];
        unsigned long long b = c[0];
        #pragma unroll
        for (int j = 1; j < 4; j++) if (c[j] > b) b = c[j];
        #pragma unroll 1
        for (int it = 0; it < TOPK; it++) {
            unsigned long long m = b;
            #pragma unroll
            for (int o = 16; o > 0; o >>= 1) {
                unsigned long long t = __shfl_xor_sync(0xffffffffu, m, o);
                if (t > m) m = t;
            }
            if (b == m) {
                #pragma unroll
                for (int j = 0; j < 4; j++) if (c[j] == m) c[j] = 0ull;
                b = c[0];
                #pragma unroll
                for (int j = 1; j < 4; j++) if (c[j] > b) b = c[j];
            }
            if (lane == 0) sbest[it] = m;
        }
        if (lane == 0) {
            float vals[TOPK];
            #pragma unroll
            for (int i = 0; i < TOPK; i++) {
                unsigned u = (unsigned)(sbest[i] >> 32);
                unsigned vb = (u & 0x80000000u) ? (u & 0x7fffffffu) : ~u;
                vals[i] = __uint_as_float(vb);
            }
            float mx = vals[0], e[TOPK], sum = 0.f;
            #pragma unroll
            for (int i = 0; i < TOPK; i++) { e[i] = expf(vals[i] - mx); sum += e[i]; }
            float inv = 1.f / sum;
            #pragma unroll
            for (int i = 0; i < TOPK; i++) {
                int id = (int)(~(unsigned)(sbest[i] & 0xffffffffull));
                g_w[row * TOPK + i]   = e[i] * inv;
                g_idx[row * TOPK + i] = id;
                g_used[id] = 1;
            }
        }
    }
}

// ---------------- kernel 5: adj_sum over R (used rows only) -----------------
__global__ __launch_bounds__(256) void k_adjsum(const float* __restrict__ adj) {
    int row = blockIdx.x >> 1;
    if (!g_used[row]) return;
    int i = row * (NKEYS / 4) + (blockIdx.x & 1) * 256 + threadIdx.x;
    const float4* a = (const float4*)adj;
    const int stride = NKEYS * NKEYS / 4;
    float4 acc = make_float4(0.f, 0.f, 0.f, 0.f);
    #pragma unroll
    for (int r = 0; r < RDIM; r++) {
        float4 v = a[r * stride + i];
        acc.x += v.x; acc.y += v.y; acc.z += v.z; acc.w += v.w;
    }
    ((float4*)g_adjsum)[i] = acc;
}

// ---------------- kernel 6: nei gather -> hi/lo bf16 planes -----------------
__global__ __launch_bounds__(256) void k_nei() {
    int row = blockIdx.x;
    int tid = threadIdx.x;
    __shared__ float sw[TOPK];
    __shared__ int   si[TOPK];
    if (tid < TOPK) { sw[tid] = g_w[row * TOPK + tid]; si[tid] = g_idx[row * TOPK + tid]; }
    __syncthreads();
    int n0 = blockIdx.y * (NKEYS / 2) + tid * 4;
    float4 a0 = make_float4(0.f, 0.f, 0.f, 0.f);
    #pragma unroll
    for (int kk = 0; kk < TOPK; kk++) {
        float wv = sw[kk];
        float4 v0 = *(const float4*)&g_adjsum[si[kk] * NKEYS + n0];
        a0.x = fmaf(wv, v0.x, a0.x); a0.y = fmaf(wv, v0.y, a0.y);
        a0.z = fmaf(wv, v0.z, a0.z); a0.w = fmaf(wv, v0.w, a0.w);
    }
    uint2 H, L;
    H.x = pack_hi2(a0.x, a0.y); H.y = pack_hi2(a0.z, a0.w);
    L.x = pack_lo2(a0.x, a0.y); L.y = pack_lo2(a0.z, a0.w);
    *(uint2*)&g_neih[row * NKEYS + n0] = H;
    *(uint2*)&g_neil[row * NKEYS + n0] = L;
}

// ---------------- kernel 7: reduce split buffers -> d_out -------------------
__global__ __launch_bounds__(256) void k_reduce(float* __restrict__ out) {
    int i4 = blockIdx.x * 256 + threadIdx.x;       // < 49152 float4s
    const float4* p = (const float4*)g_outp;
    float4 a = make_float4(0.f, 0.f, 0.f, 0.f);
    #pragma unroll
    for (int z = 0; z < SPLIT2; z++) {
        float4 v = p[z * (MROWS * DDIM / 4) + i4];
        a.x += v.x; a.y += v.y; a.z += v.z; a.w += v.w;
    }
    ((float4*)out)[i4] = a;
}

// ---------------- launch ----------------------------------------------------
extern "C" void kernel_launch(void* const* d_in, const int* in_sizes, int n_in,
                              void* d_out, int out_size) {
    const float* positions  = (const float*)d_in[0];   // [4,64,768]
    const float* keys_param = (const float*)d_in[1];   // [2048,768]
    const float* adjacency  = (const float*)d_in[2];   // [12,2048,2048]
    float* out = (float*)d_out;                        // [4,64,768]

    __nv_bfloat16 *p_kh, *p_kl, *p_kth, *p_ktl, *p_ph, *p_pl, *p_nh, *p_nl;
    float *p_sc4, *p_outp;
    cudaGetSymbolAddress((void**)&p_kh,   g_keysh);
    cudaGetSymbolAddress((void**)&p_kl,   g_keysl);
    cudaGetSymbolAddress((void**)&p_kth,  g_keysTh);
    cudaGetSymbolAddress((void**)&p_ktl,  g_keysTl);
    cudaGetSymbolAddress((void**)&p_ph,   g_posh);
    cudaGetSymbolAddress((void**)&p_pl,   g_posl);
    cudaGetSymbolAddress((void**)&p_nh,   g_neih);
    cudaGetSymbolAddress((void**)&p_nl,   g_neil);
    cudaGetSymbolAddress((void**)&p_sc4,  g_scores4);
    cudaGetSymbolAddress((void**)&p_outp, g_outp);

    const int GEMM_SMEM = 2 * STAGE_B;      // 131072 bytes
    static int smem_set = 0;
    if (!smem_set) {
        cudaFuncSetAttribute(k_gemm, cudaFuncAttributeMaxDynamicSharedMemorySize,
                             GEMM_SMEM);
        smem_set = 1;
    }

    // 1. fused: normalize keys -> hi/lo (+used-mask reset) and positions -> hi/lo
    k_norm_prep<<<NKEYS + MROWS * DDIM / 4 / 256, 256>>>(keys_param, positions);
    // 2. keys transpose (for GEMM2's NT form)
    {
        dim3 grid(DDIM / 32, NKEYS / 32);
        k_transpose<<<grid, dim3(256)>>>();
    }
    // 3. scores = positions @ keys^T  (M=256, N=2048, K=768, split-K=4 -> 128 CTAs)
    {
        dim3 grid(NKEYS / 128, MROWS / 128, SPLIT1);
        k_gemm<<<grid, 256, GEMM_SMEM>>>(p_ph, p_pl, p_kh, p_kl, p_sc4,
                                         DDIM, NKEYS);
    }
    // 4. top-16 + softmax (marks used rows)
    k_topk<<<MROWS, 256>>>();
    // 5. adjacency reduction over R (used rows only)
    k_adjsum<<<NKEYS * 2, 256>>>(adjacency);
    // 6. nei gather -> hi/lo planes
    {
        dim3 grid(MROWS, 2);
        k_nei<<<grid, 256>>>();
    }
    // 7. out = nei @ keys  (M=256, N=768, K=2048, split-K=12 -> 144 CTAs)
    {
        dim3 grid(DDIM / 128, MROWS / 128, SPLIT2);
        k_gemm<<<grid, 256, GEMM_SMEM>>>(p_nh, p_nl, p_kth, p_ktl, p_outp,
                                         NKEYS, DDIM);
    }
    // 8. reduce split buffers into d_out
    k_reduce<<<MROWS * DDIM / 4 / 256, 256>>>(out);
}